// round 2
// baseline (speedup 1.0000x reference)
#include <cuda_runtime.h>
#include <cuda_bf16.h>
#include <math.h>

// WarpTranspose: adjoint of bilinear warp.
// grad_out: [B,H,W,C] f32, u: [B,H,W,2] f32 (dx,dy), out: [B,H,W,C] f32
// For each source pixel p=(b,y,x): gx=x+dx, gy=y+dy, bilinear scatter-add of
// w_corner * grad_out[p,:] into the 4 integer corners (zero-boundary mask).

#define H_DIM 512
#define W_DIM 512
#define C_DIM 16

__global__ void __launch_bounds__(256)
warp_transpose_scatter(const float* __restrict__ grad_out,
                       const float* __restrict__ u,
                       float* __restrict__ out,
                       int total_quads) {
    int gid = blockIdx.x * blockDim.x + threadIdx.x;
    if (gid >= total_quads) return;

    const int quad = gid & 3;      // which float4 of the 16 channels
    const int p    = gid >> 2;     // pixel index: ((b*H + y)*W + x)

    const int x = p & (W_DIM - 1);
    const int y = (p >> 9) & (H_DIM - 1);

    // flow
    const float2 uv = __ldg((const float2*)(u + 2 * p));
    const float gx = (float)x + uv.x;
    const float gy = (float)y + uv.y;

    const float x0f = floorf(gx);
    const float y0f = floorf(gy);
    const float wx = gx - x0f;
    const float wy = gy - y0f;
    const int x0 = (int)x0f;
    const int y0 = (int)y0f;
    const int x1 = x0 + 1;
    const int y1 = y0 + 1;

    // this thread's channel-quad of grad_out (16B coalesced across quad lanes)
    const float4 g = __ldg((const float4*)(grad_out + (size_t)p * C_DIM + quad * 4));

    const bool vx0 = (x0 >= 0) && (x0 < W_DIM);
    const bool vx1 = (x1 >= 0) && (x1 < W_DIM);
    const bool vy0 = (y0 >= 0) && (y0 < H_DIM);
    const bool vy1 = (y1 >= 0) && (y1 < H_DIM);

    const float w00 = (1.0f - wy) * (1.0f - wx);
    const float w01 = (1.0f - wy) * wx;
    const float w10 = wy * (1.0f - wx);
    const float w11 = wy * wx;

    // relative addressing within the same batch image:
    // out base for (b, yi, xi) = (p + (yi - y)*W + (xi - x)) * C + quad*4
    const int dy0 = (y0 - y) * W_DIM;
    const int dy1 = (y1 - y) * W_DIM;
    const int dx0 = x0 - x;
    const int dx1 = x1 - x;
    float* outq = out + (size_t)p * C_DIM + quad * 4;

    if (vy0 & vx0) {
        float4 v = make_float4(g.x * w00, g.y * w00, g.z * w00, g.w * w00);
        atomicAdd((float4*)(outq + (size_t)(dy0 + dx0) * C_DIM), v);
    }
    if (vy0 & vx1) {
        float4 v = make_float4(g.x * w01, g.y * w01, g.z * w01, g.w * w01);
        atomicAdd((float4*)(outq + (size_t)(dy0 + dx1) * C_DIM), v);
    }
    if (vy1 & vx0) {
        float4 v = make_float4(g.x * w10, g.y * w10, g.z * w10, g.w * w10);
        atomicAdd((float4*)(outq + (size_t)(dy1 + dx0) * C_DIM), v);
    }
    if (vy1 & vx1) {
        float4 v = make_float4(g.x * w11, g.y * w11, g.z * w11, g.w * w11);
        atomicAdd((float4*)(outq + (size_t)(dy1 + dx1) * C_DIM), v);
    }
}

extern "C" void kernel_launch(void* const* d_in, const int* in_sizes, int n_in,
                              void* d_out, int out_size) {
    const float* grad_out = (const float*)d_in[0];
    const float* u        = (const float*)d_in[1];
    // d_in[2] (x) is unused: only defines output shape.
    float* out = (float*)d_out;

    const int B = in_sizes[1] / (H_DIM * W_DIM * 2);
    const int total_pixels = B * H_DIM * W_DIM;
    const int total_quads = total_pixels * 4;

    // zero the (poisoned) output — legal graph node, no allocation
    cudaMemsetAsync(d_out, 0, (size_t)out_size * sizeof(float), 0);

    const int block = 256;
    const int grid = (total_quads + block - 1) / block;
    warp_transpose_scatter<<<grid, block>>>(grad_out, u, out, total_quads);
}